// round 5
// baseline (speedup 1.0000x reference)
#include <cuda_runtime.h>
#include <cuda_bf16.h>
#include <cstdint>

// FracDownSample fused kernel v4 (sm_103a) — bf16 GEMM + register-hoisted
// aggregation weights.
// x:[16,256,128,128] f32, w_key:[64,256], w_sim:[4,64] -> out:[16,256,64,64] f32
//
// One CTA = (n, hb, wq): 4 pixel rows x 32 cols = 128 pixels = 8 windows.
//  Phase 1: key GEMM [128 x 64 x 256] bf16 mma.m16n8k16, warp tiles m32 x n32,
//           fragment-packed smem, LDG prefetch distance = 1 iteration.
//  Phase 2: kq = w_sim * relu(key), shuffle + 2-plane smem reduce.
//  Phase 3: per-window softmax -> weights written to 16B-aligned aw[] layout.
//  Phase 4: aggregation, weights hoisted to registers (4xLDS.128 per i),
//           channel-pass inner loop (MLP=8 on L2-hot LDG.128).

#define H_ 128
#define W_ 128
#define C_ 256
#define HW (H_ * W_)
#define KQ_STRIDE 5

#define BP_WORDS  8192           // 16 ksteps * 8 ntiles * 64 words (bf16x2)
#define ACH_WORDS 1024           // 8 mtiles * 128 words per 16-ch chunk

__device__ __forceinline__ uint32_t packbf(float lo, float hi) {
    __nv_bfloat162 v = __floats2bfloat162_rn(lo, hi);
    return *reinterpret_cast<uint32_t*>(&v);
}

__global__ __launch_bounds__(256, 3)
void frac_downsample_kernel(const float* __restrict__ x,
                            const float* __restrict__ w_key,
                            const float* __restrict__ w_sim,
                            float* __restrict__ out) {
    extern __shared__ uint32_t smem[];
    uint32_t* Bp     = smem;                          // 8192 w (32 KB)
    uint32_t* As     = Bp + BP_WORDS;                 // 2*1024 w (8 KB)
    float*    kq2    = (float*)(As + 2 * ACH_WORDS);  // 2 planes * 128*5
    float*    wsim_s = kq2 + 2 * 128 * KQ_STRIDE;     // 256
    float*    aw     = wsim_s + 256;                  // 16*8*4 = 512 (16B-aligned)

    const int tid = threadIdx.x;
    const int bid = blockIdx.x;
    const int n  = bid >> 7;
    const int hb = (bid >> 2) & 31;
    const int wq = bid & 3;

    const float* xbase = x + ((size_t)n * C_ * H_ + (size_t)hb * 4) * W_ + wq * 32;

    // ---- stage B (w_key) fragment-packed bf16x2 ----
    {
        const int c    = (tid & 127) * 2;
        const int s    = c >> 4;
        const int kkc  = c & 15;
        const int tigc = (kkc >> 1) & 3;
        const int kh   = kkc >> 3;
        const int rb   = tid >> 7;
        #pragma unroll 8
        for (int rr = 0; rr < 32; rr++) {
            int r = rr * 2 + rb;
            int nt = r >> 3, g = r & 7;
            Bp[(s * 8 + nt) * 64 + (g * 4 + tigc) * 2 + kh] =
                packbf(w_key[r * 256 + c], w_key[r * 256 + c + 1]);
        }
    }
    wsim_s[tid] = w_sim[tid];

    // ---- per-thread A staging offsets ----
    const int m  = tid & 127;
    const int h  = tid >> 7;
    const uint32_t pixoff = (uint32_t)(m >> 5) * W_ + (m & 31);
    uint32_t goff[4];
    int      sw[4];
    {
        const int mtile = m >> 4, ml = m & 15;
        const int gid_s = ml & 7, b1 = ml >> 3;
        #pragma unroll
        for (int i = 0; i < 4; i++) {
            int kkp = 2 * i + h;
            int tig_s = kkp & 3, kh_s = kkp >> 2;
            int lane_r = ((gid_s * 4 + tig_s) + mtile * 2) & 31;
            sw[i]   = mtile * 128 + kh_s * 64 + lane_r * 2 + b1;
            goff[i] = (uint32_t)(4 * i + 2 * h) * HW + pixoff;
        }
    }

    // ---- prologue: chunk 0 direct, chunk 1 into prefetch regs ----
    float pre[8];
    #pragma unroll
    for (int i = 0; i < 4; i++)
        As[sw[i]] = packbf(xbase[goff[i]], xbase[goff[i] + HW]);
    {
        const float* xc = xbase + 16 * HW;
        #pragma unroll
        for (int i = 0; i < 4; i++) {
            pre[2 * i]     = xc[goff[i]];
            pre[2 * i + 1] = xc[goff[i] + HW];
        }
    }
    __syncthreads();

    const int warp = tid >> 5, lane = tid & 31;
    const int warp_m = warp & 3;
    const int warp_n = warp >> 2;
    const int gid = lane >> 2, tig = lane & 3;

    float acc[2][4][4];
    #pragma unroll
    for (int a = 0; a < 2; a++)
        #pragma unroll
        for (int b = 0; b < 4; b++)
            acc[a][b][0] = acc[a][b][1] = acc[a][b][2] = acc[a][b][3] = 0.f;

    // ---- Phase 1: 16 ksteps, prefetch distance = 1 iteration ----
    for (int c = 0; c < 16; c++) {
        if (c + 1 < 16) {
            uint32_t* An = As + ((c + 1) & 1) * ACH_WORDS;
            #pragma unroll
            for (int i = 0; i < 4; i++)
                An[sw[i]] = packbf(pre[2 * i], pre[2 * i + 1]);
        }
        if (c + 2 < 16) {
            const float* xn = xbase + (size_t)(c + 2) * 16 * HW;
            #pragma unroll
            for (int i = 0; i < 4; i++) {
                pre[2 * i]     = xn[goff[i]];
                pre[2 * i + 1] = xn[goff[i] + HW];
            }
        }
        const uint32_t* Ac = As + (c & 1) * ACH_WORDS;
        uint2 afr[2][2];
        #pragma unroll
        for (int mtl = 0; mtl < 2; mtl++) {
            int mt = warp_m * 2 + mtl;
            int lr = ((lane + mt * 2) & 31) * 2;
            afr[mtl][0] = *reinterpret_cast<const uint2*>(Ac + mt * 128 + lr);
            afr[mtl][1] = *reinterpret_cast<const uint2*>(Ac + mt * 128 + 64 + lr);
        }
        uint2 bfr[4];
        #pragma unroll
        for (int ntl = 0; ntl < 4; ntl++)
            bfr[ntl] = *reinterpret_cast<const uint2*>(
                Bp + (c * 8 + warp_n * 4 + ntl) * 64 + lane * 2);
        #pragma unroll
        for (int mtl = 0; mtl < 2; mtl++)
            #pragma unroll
            for (int ntl = 0; ntl < 4; ntl++) {
                asm volatile(
                    "mma.sync.aligned.m16n8k16.row.col.f32.bf16.bf16.f32 "
                    "{%0,%1,%2,%3}, {%4,%5,%6,%7}, {%8,%9}, {%0,%1,%2,%3};"
                    : "+f"(acc[mtl][ntl][0]), "+f"(acc[mtl][ntl][1]),
                      "+f"(acc[mtl][ntl][2]), "+f"(acc[mtl][ntl][3])
                    : "r"(afr[mtl][0].x), "r"(afr[mtl][0].y),
                      "r"(afr[mtl][1].x), "r"(afr[mtl][1].y),
                      "r"(bfr[ntl].x), "r"(bfr[ntl].y));
            }
        __syncthreads();
    }

    // ---- Phase 2: kq = w_sim * relu(key) ----
    #pragma unroll
    for (int mtl = 0; mtl < 2; mtl++) {
        float pa[4] = {0, 0, 0, 0}, pb[4] = {0, 0, 0, 0};
        #pragma unroll
        for (int ntl = 0; ntl < 4; ntl++) {
            int col0 = warp_n * 32 + ntl * 8 + 2 * tig;
            float v0 = fmaxf(acc[mtl][ntl][0], 0.f);
            float v1 = fmaxf(acc[mtl][ntl][1], 0.f);
            float v2 = fmaxf(acc[mtl][ntl][2], 0.f);
            float v3 = fmaxf(acc[mtl][ntl][3], 0.f);
            #pragma unroll
            for (int s = 0; s < 4; s++) {
                float w0 = wsim_s[s * 64 + col0];
                float w1 = wsim_s[s * 64 + col0 + 1];
                pa[s] += v0 * w0 + v1 * w1;
                pb[s] += v2 * w0 + v3 * w1;
            }
        }
        #pragma unroll
        for (int s = 0; s < 4; s++) {
            pa[s] += __shfl_xor_sync(0xffffffffu, pa[s], 1);
            pa[s] += __shfl_xor_sync(0xffffffffu, pa[s], 2);
            pb[s] += __shfl_xor_sync(0xffffffffu, pb[s], 1);
            pb[s] += __shfl_xor_sync(0xffffffffu, pb[s], 2);
        }
        float va = (tig == 0) ? pa[0] : (tig == 1) ? pa[1] : (tig == 2) ? pa[2] : pa[3];
        float vb = (tig == 0) ? pb[0] : (tig == 1) ? pb[1] : (tig == 2) ? pb[2] : pb[3];
        int r0 = warp_m * 32 + mtl * 16 + gid;
        float* plane = kq2 + warp_n * 128 * KQ_STRIDE;
        plane[r0 * KQ_STRIDE + tig]       = va;
        plane[(r0 + 8) * KQ_STRIDE + tig] = vb;
    }
    __syncthreads();

    // ---- Phase 3: per-window softmax; output to aw[(p*8+win)*4+q] ----
    if (tid < 32) {
        int win = tid >> 2, s = tid & 3;
        float vals[16];
        float mx = -3.4e38f;
        #pragma unroll
        for (int p = 0; p < 16; p++) {
            int mm = (p >> 2) * 32 + win * 4 + (p & 3);
            float v = (kq2[mm * KQ_STRIDE + s] +
                       kq2[128 * KQ_STRIDE + mm * KQ_STRIDE + s]) * 0.25f;
            vals[p] = v;
            mx = fmaxf(mx, v);
        }
        float sum = 0.f;
        #pragma unroll
        for (int p = 0; p < 16; p++) { vals[p] = __expf(vals[p] - mx); sum += vals[p]; }
        float inv = 1.f / sum;
        #pragma unroll
        for (int p = 0; p < 16; p++)
            aw[(p * 8 + win) * 4 + s] = vals[p] * inv;
    }
    __syncthreads();

    // ---- Phase 4: aggregation, weights hoisted to registers ----
    {
        const int win = tid & 7;
        const int cb  = tid >> 3;
        const float* xa = x + (size_t)n * C_ * HW + (size_t)(hb * 4) * W_
                          + wq * 32 + win * 4 + (size_t)cb * HW;
        float o[8][4];
        #pragma unroll
        for (int pass = 0; pass < 8; pass++)
            o[pass][0] = o[pass][1] = o[pass][2] = o[pass][3] = 0.f;

        #pragma unroll
        for (int i = 0; i < 4; i++) {
            float4 wv[4];
            #pragma unroll
            for (int j = 0; j < 4; j++)
                wv[j] = *reinterpret_cast<const float4*>(
                    aw + ((i * 4 + j) * 8 + win) * 4);
            #pragma unroll
            for (int pass = 0; pass < 8; pass++) {
                float4 v = *reinterpret_cast<const float4*>(
                    xa + (size_t)(pass * 32) * HW + i * W_);
                o[pass][0] += v.x * wv[0].x + v.y * wv[1].x + v.z * wv[2].x + v.w * wv[3].x;
                o[pass][1] += v.x * wv[0].y + v.y * wv[1].y + v.z * wv[2].y + v.w * wv[3].y;
                o[pass][2] += v.x * wv[0].z + v.y * wv[1].z + v.z * wv[2].z + v.w * wv[3].z;
                o[pass][3] += v.x * wv[0].w + v.y * wv[1].w + v.z * wv[2].w + v.w * wv[3].w;
            }
        }

        float* ob = out + ((size_t)n * C_ * 64 + hb * 2) * 64 + wq * 16 + win * 2
                  + (size_t)cb * 64 * 64;
        #pragma unroll
        for (int pass = 0; pass < 8; pass++) {
            float* op = ob + (size_t)(pass * 32) * 64 * 64;
            *reinterpret_cast<float2*>(op)      = make_float2(o[pass][0], o[pass][1]);
            *reinterpret_cast<float2*>(op + 64) = make_float2(o[pass][2], o[pass][3]);
        }
    }
}

extern "C" void kernel_launch(void* const* d_in, const int* in_sizes, int n_in,
                              void* d_out, int out_size) {
    const float* x  = (const float*)d_in[0];
    const float* wk = (const float*)d_in[1];
    const float* ws = (const float*)d_in[2];
    float* out = (float*)d_out;

    const int smem_bytes = (BP_WORDS + 2 * ACH_WORDS) * 4
                         + (2 * 128 * KQ_STRIDE + 256 + 512) * 4;   // 49152 B
    cudaFuncSetAttribute(frac_downsample_kernel,
                         cudaFuncAttributeMaxDynamicSharedMemorySize, smem_bytes);

    frac_downsample_kernel<<<2048, 256, smem_bytes>>>(x, wk, ws, out);
}

// round 6
// speedup vs baseline: 1.2723x; 1.2723x over previous
#include <cuda_runtime.h>
#include <cuda_bf16.h>
#include <cstdint>

// FracDownSample fused kernel v5 (sm_103a) — bf16 GEMM; phase-4 = v3 loop
// order (pass-outer, 4 live accumulators) + vectorized LDS.128 weight loads.
// x:[16,256,128,128] f32, w_key:[64,256], w_sim:[4,64] -> out:[16,256,64,64] f32

#define H_ 128
#define W_ 128
#define C_ 256
#define HW (H_ * W_)
#define KQ_STRIDE 5

#define BP_WORDS  8192           // 16 ksteps * 8 ntiles * 64 words (bf16x2)
#define ACH_WORDS 1024           // 8 mtiles * 128 words per 16-ch chunk

__device__ __forceinline__ uint32_t packbf(float lo, float hi) {
    __nv_bfloat162 v = __floats2bfloat162_rn(lo, hi);
    return *reinterpret_cast<uint32_t*>(&v);
}

__global__ __launch_bounds__(256, 3)
void frac_downsample_kernel(const float* __restrict__ x,
                            const float* __restrict__ w_key,
                            const float* __restrict__ w_sim,
                            float* __restrict__ out) {
    extern __shared__ uint32_t smem[];
    uint32_t* Bp     = smem;                          // 8192 w (32 KB)
    uint32_t* As     = Bp + BP_WORDS;                 // 2*1024 w (8 KB)
    float*    kq2    = (float*)(As + 2 * ACH_WORDS);  // 2 planes * 128*5
    float*    wsim_s = kq2 + 2 * 128 * KQ_STRIDE;     // 256
    float*    aw     = wsim_s + 256;                  // 16*8*4 floats, 16B-aligned

    const int tid = threadIdx.x;
    const int bid = blockIdx.x;
    const int n  = bid >> 7;
    const int hb = (bid >> 2) & 31;
    const int wq = bid & 3;

    const float* xbase = x + ((size_t)n * C_ * H_ + (size_t)hb * 4) * W_ + wq * 32;

    // ---- stage B (w_key) fragment-packed bf16x2 ----
    {
        const int c    = (tid & 127) * 2;
        const int s    = c >> 4;
        const int kkc  = c & 15;
        const int tigc = (kkc >> 1) & 3;
        const int kh   = kkc >> 3;
        const int rb   = tid >> 7;
        #pragma unroll 8
        for (int rr = 0; rr < 32; rr++) {
            int r = rr * 2 + rb;
            int nt = r >> 3, g = r & 7;
            Bp[(s * 8 + nt) * 64 + (g * 4 + tigc) * 2 + kh] =
                packbf(w_key[r * 256 + c], w_key[r * 256 + c + 1]);
        }
    }
    wsim_s[tid] = w_sim[tid];

    // ---- per-thread A staging offsets ----
    const int m  = tid & 127;
    const int h  = tid >> 7;
    const uint32_t pixoff = (uint32_t)(m >> 5) * W_ + (m & 31);
    uint32_t goff[4];
    int      sw[4];
    {
        const int mtile = m >> 4, ml = m & 15;
        const int gid_s = ml & 7, b1 = ml >> 3;
        #pragma unroll
        for (int i = 0; i < 4; i++) {
            int kkp = 2 * i + h;
            int tig_s = kkp & 3, kh_s = kkp >> 2;
            int lane_r = ((gid_s * 4 + tig_s) + mtile * 2) & 31;
            sw[i]   = mtile * 128 + kh_s * 64 + lane_r * 2 + b1;
            goff[i] = (uint32_t)(4 * i + 2 * h) * HW + pixoff;
        }
    }

    // ---- prologue: chunk 0 direct, chunk 1 into prefetch regs ----
    float pre[8];
    #pragma unroll
    for (int i = 0; i < 4; i++)
        As[sw[i]] = packbf(xbase[goff[i]], xbase[goff[i] + HW]);
    {
        const float* xc = xbase + 16 * HW;
        #pragma unroll
        for (int i = 0; i < 4; i++) {
            pre[2 * i]     = xc[goff[i]];
            pre[2 * i + 1] = xc[goff[i] + HW];
        }
    }
    __syncthreads();

    const int warp = tid >> 5, lane = tid & 31;
    const int warp_m = warp & 3;
    const int warp_n = warp >> 2;
    const int gid = lane >> 2, tig = lane & 3;

    float acc[2][4][4];
    #pragma unroll
    for (int a = 0; a < 2; a++)
        #pragma unroll
        for (int b = 0; b < 4; b++)
            acc[a][b][0] = acc[a][b][1] = acc[a][b][2] = acc[a][b][3] = 0.f;

    // ---- Phase 1: 16 ksteps, prefetch distance = 1 iteration ----
    for (int c = 0; c < 16; c++) {
        if (c + 1 < 16) {
            uint32_t* An = As + ((c + 1) & 1) * ACH_WORDS;
            #pragma unroll
            for (int i = 0; i < 4; i++)
                An[sw[i]] = packbf(pre[2 * i], pre[2 * i + 1]);
        }
        if (c + 2 < 16) {
            const float* xn = xbase + (size_t)(c + 2) * 16 * HW;
            #pragma unroll
            for (int i = 0; i < 4; i++) {
                pre[2 * i]     = xn[goff[i]];
                pre[2 * i + 1] = xn[goff[i] + HW];
            }
        }
        const uint32_t* Ac = As + (c & 1) * ACH_WORDS;
        uint2 afr[2][2];
        #pragma unroll
        for (int mtl = 0; mtl < 2; mtl++) {
            int mt = warp_m * 2 + mtl;
            int lr = ((lane + mt * 2) & 31) * 2;
            afr[mtl][0] = *reinterpret_cast<const uint2*>(Ac + mt * 128 + lr);
            afr[mtl][1] = *reinterpret_cast<const uint2*>(Ac + mt * 128 + 64 + lr);
        }
        uint2 bfr[4];
        #pragma unroll
        for (int ntl = 0; ntl < 4; ntl++)
            bfr[ntl] = *reinterpret_cast<const uint2*>(
                Bp + (c * 8 + warp_n * 4 + ntl) * 64 + lane * 2);
        #pragma unroll
        for (int mtl = 0; mtl < 2; mtl++)
            #pragma unroll
            for (int ntl = 0; ntl < 4; ntl++) {
                asm volatile(
                    "mma.sync.aligned.m16n8k16.row.col.f32.bf16.bf16.f32 "
                    "{%0,%1,%2,%3}, {%4,%5,%6,%7}, {%8,%9}, {%0,%1,%2,%3};"
                    : "+f"(acc[mtl][ntl][0]), "+f"(acc[mtl][ntl][1]),
                      "+f"(acc[mtl][ntl][2]), "+f"(acc[mtl][ntl][3])
                    : "r"(afr[mtl][0].x), "r"(afr[mtl][0].y),
                      "r"(afr[mtl][1].x), "r"(afr[mtl][1].y),
                      "r"(bfr[ntl].x), "r"(bfr[ntl].y));
            }
        __syncthreads();
    }

    // ---- Phase 2: kq = w_sim * relu(key) ----
    #pragma unroll
    for (int mtl = 0; mtl < 2; mtl++) {
        float pa[4] = {0, 0, 0, 0}, pb[4] = {0, 0, 0, 0};
        #pragma unroll
        for (int ntl = 0; ntl < 4; ntl++) {
            int col0 = warp_n * 32 + ntl * 8 + 2 * tig;
            float v0 = fmaxf(acc[mtl][ntl][0], 0.f);
            float v1 = fmaxf(acc[mtl][ntl][1], 0.f);
            float v2 = fmaxf(acc[mtl][ntl][2], 0.f);
            float v3 = fmaxf(acc[mtl][ntl][3], 0.f);
            #pragma unroll
            for (int s = 0; s < 4; s++) {
                float w0 = wsim_s[s * 64 + col0];
                float w1 = wsim_s[s * 64 + col0 + 1];
                pa[s] += v0 * w0 + v1 * w1;
                pb[s] += v2 * w0 + v3 * w1;
            }
        }
        #pragma unroll
        for (int s = 0; s < 4; s++) {
            pa[s] += __shfl_xor_sync(0xffffffffu, pa[s], 1);
            pa[s] += __shfl_xor_sync(0xffffffffu, pa[s], 2);
            pb[s] += __shfl_xor_sync(0xffffffffu, pb[s], 1);
            pb[s] += __shfl_xor_sync(0xffffffffu, pb[s], 2);
        }
        float va = (tig == 0) ? pa[0] : (tig == 1) ? pa[1] : (tig == 2) ? pa[2] : pa[3];
        float vb = (tig == 0) ? pb[0] : (tig == 1) ? pb[1] : (tig == 2) ? pb[2] : pb[3];
        int r0 = warp_m * 32 + mtl * 16 + gid;
        float* plane = kq2 + warp_n * 128 * KQ_STRIDE;
        plane[r0 * KQ_STRIDE + tig]       = va;
        plane[(r0 + 8) * KQ_STRIDE + tig] = vb;
    }
    __syncthreads();

    // ---- Phase 3: per-window softmax; output to aw[(p*8+win)*4+q] ----
    if (tid < 32) {
        int win = tid >> 2, s = tid & 3;
        float vals[16];
        float mx = -3.4e38f;
        #pragma unroll
        for (int p = 0; p < 16; p++) {
            int mm = (p >> 2) * 32 + win * 4 + (p & 3);
            float v = (kq2[mm * KQ_STRIDE + s] +
                       kq2[128 * KQ_STRIDE + mm * KQ_STRIDE + s]) * 0.25f;
            vals[p] = v;
            mx = fmaxf(mx, v);
        }
        float sum = 0.f;
        #pragma unroll
        for (int p = 0; p < 16; p++) { vals[p] = __expf(vals[p] - mx); sum += vals[p]; }
        float inv = 1.f / sum;
        #pragma unroll
        for (int p = 0; p < 16; p++)
            aw[(p * 8 + win) * 4 + s] = vals[p] * inv;
    }
    __syncthreads();

    // ---- Phase 4: aggregation, pass-outer (4 live accumulators),
    //      weights via 4x LDS.128 per (pass, i) ----
    {
        const int win = tid & 7;
        const int cb  = tid >> 3;
        const float* xa = x + (size_t)n * C_ * HW + (size_t)(hb * 4) * W_
                          + wq * 32 + win * 4;
        float* ob = out + ((size_t)n * C_ * 64 + hb * 2) * 64 + wq * 16 + win * 2;
        const float* awin = aw + win * 4;
        #pragma unroll
        for (int pass = 0; pass < 8; pass++) {
            int c = pass * 32 + cb;
            const float* xp = xa + (size_t)c * HW;
            float o0 = 0.f, o1 = 0.f, o2 = 0.f, o3 = 0.f;
            #pragma unroll
            for (int i = 0; i < 4; i++) {
                float4 v = *reinterpret_cast<const float4*>(xp + i * W_);
                float4 w0 = *reinterpret_cast<const float4*>(awin + (i * 4 + 0) * 32);
                float4 w1 = *reinterpret_cast<const float4*>(awin + (i * 4 + 1) * 32);
                float4 w2 = *reinterpret_cast<const float4*>(awin + (i * 4 + 2) * 32);
                float4 w3 = *reinterpret_cast<const float4*>(awin + (i * 4 + 3) * 32);
                o0 += v.x * w0.x + v.y * w1.x + v.z * w2.x + v.w * w3.x;
                o1 += v.x * w0.y + v.y * w1.y + v.z * w2.y + v.w * w3.y;
                o2 += v.x * w0.z + v.y * w1.z + v.z * w2.z + v.w * w3.z;
                o3 += v.x * w0.w + v.y * w1.w + v.z * w2.w + v.w * w3.w;
            }
            float* op = ob + (size_t)c * 64 * 64;
            *reinterpret_cast<float2*>(op)      = make_float2(o0, o1);
            *reinterpret_cast<float2*>(op + 64) = make_float2(o2, o3);
        }
    }
}

extern "C" void kernel_launch(void* const* d_in, const int* in_sizes, int n_in,
                              void* d_out, int out_size) {
    const float* x  = (const float*)d_in[0];
    const float* wk = (const float*)d_in[1];
    const float* ws = (const float*)d_in[2];
    float* out = (float*)d_out;

    const int smem_bytes = (BP_WORDS + 2 * ACH_WORDS) * 4
                         + (2 * 128 * KQ_STRIDE + 256 + 512) * 4;   // 49152 B
    cudaFuncSetAttribute(frac_downsample_kernel,
                         cudaFuncAttributeMaxDynamicSharedMemorySize, smem_bytes);

    frac_downsample_kernel<<<2048, 256, smem_bytes>>>(x, wk, ws, out);
}

// round 7
// speedup vs baseline: 1.3134x; 1.0323x over previous
#include <cuda_runtime.h>
#include <cuda_bf16.h>
#include <cstdint>

// FracDownSample fused kernel v6 (sm_103a).
// x:[16,256,128,128] f32, w_key:[64,256], w_sim:[4,64] -> out:[16,256,64,64] f32
//
// vs v5: phase-1 uses 8 super-iterations (2 ksteps per barrier) over a
// 4-buffer smem ring (same 8 prefetch regs, turned over twice per iter);
// phase-4 interleaves 2 channel-passes per weight load (half the weight LDS,
// double the LDG MLP).

#define H_ 128
#define W_ 128
#define C_ 256
#define HW (H_ * W_)
#define KQ_STRIDE 5

#define BP_WORDS  8192           // 16 ksteps * 8 ntiles * 64 words (bf16x2)
#define ACH_WORDS 1024           // one 16-ch chunk, fragment-packed bf16x2

__device__ __forceinline__ uint32_t packbf(float lo, float hi) {
    __nv_bfloat162 v = __floats2bfloat162_rn(lo, hi);
    return *reinterpret_cast<uint32_t*>(&v);
}

__global__ __launch_bounds__(256, 3)
void frac_downsample_kernel(const float* __restrict__ x,
                            const float* __restrict__ w_key,
                            const float* __restrict__ w_sim,
                            float* __restrict__ out) {
    extern __shared__ uint32_t smem[];
    uint32_t* Bp     = smem;                          // 8192 w (32 KB)
    uint32_t* As     = Bp + BP_WORDS;                 // 4*1024 w (16 KB ring)
    float*    kq2    = (float*)(As + 4 * ACH_WORDS);  // 2 planes * 128*5
    float*    wsim_s = kq2 + 2 * 128 * KQ_STRIDE;     // 256
    float*    aw     = wsim_s + 256;                  // 16*8*4 floats, 16B-aligned

    const int tid = threadIdx.x;
    const int bid = blockIdx.x;
    const int n  = bid >> 7;
    const int hb = (bid >> 2) & 31;
    const int wq = bid & 3;

    const float* xbase = x + ((size_t)n * C_ * H_ + (size_t)hb * 4) * W_ + wq * 32;

    // ---- stage B (w_key) fragment-packed bf16x2 ----
    {
        const int c    = (tid & 127) * 2;
        const int s    = c >> 4;
        const int kkc  = c & 15;
        const int tigc = (kkc >> 1) & 3;
        const int kh   = kkc >> 3;
        const int rb   = tid >> 7;
        #pragma unroll 8
        for (int rr = 0; rr < 32; rr++) {
            int r = rr * 2 + rb;
            int nt = r >> 3, g = r & 7;
            Bp[(s * 8 + nt) * 64 + (g * 4 + tigc) * 2 + kh] =
                packbf(w_key[r * 256 + c], w_key[r * 256 + c + 1]);
        }
    }
    wsim_s[tid] = w_sim[tid];

    // ---- per-thread A staging geometry ----
    const int m  = tid & 127;          // pixel within tile
    const int h  = tid >> 7;           // channel-pair half
    const float* xpix = xbase + (size_t)(m >> 5) * W_ + (m & 31)
                      + (size_t)(2 * h) * HW;
    int sw[4];
    {
        const int mtile = m >> 4, ml = m & 15;
        const int gid_s = ml & 7, b1 = ml >> 3;
        #pragma unroll
        for (int i = 0; i < 4; i++) {
            int kkp = 2 * i + h;
            int tig_s = kkp & 3, kh_s = kkp >> 2;
            int lane_r = ((gid_s * 4 + tig_s) + mtile * 2) & 31;
            sw[i]   = mtile * 128 + kh_s * 64 + lane_r * 2 + b1;
        }
    }

    // ---- prologue: chunks 0,1 direct to ring; chunk 2 into prefetch regs ----
    float pre[8];
    #pragma unroll
    for (int ck = 0; ck < 2; ck++) {
        const float* xc = xpix + (size_t)ck * (16 * HW);
        uint32_t* An = As + ck * ACH_WORDS;
        #pragma unroll
        for (int i = 0; i < 4; i++)
            An[sw[i]] = packbf(xc[(size_t)i * 4 * HW], xc[(size_t)i * 4 * HW + HW]);
    }
    {
        const float* xc = xpix + (size_t)2 * (16 * HW);
        #pragma unroll
        for (int i = 0; i < 4; i++) {
            pre[2 * i]     = xc[(size_t)i * 4 * HW];
            pre[2 * i + 1] = xc[(size_t)i * 4 * HW + HW];
        }
    }
    __syncthreads();

    const int warp = tid >> 5, lane = tid & 31;
    const int warp_m = warp & 3;
    const int warp_n = warp >> 2;
    const int gid = lane >> 2, tig = lane & 3;

    float acc[2][4][4];
    #pragma unroll
    for (int a = 0; a < 2; a++)
        #pragma unroll
        for (int b = 0; b < 4; b++)
            acc[a][b][0] = acc[a][b][1] = acc[a][b][2] = acc[a][b][3] = 0.f;

    // ---- Phase 1: 8 super-iterations (2 ksteps per barrier) ----
    for (int s8 = 0; s8 < 8; s8++) {
        #pragma unroll
        for (int half = 0; half < 2; half++) {
            const int c = 2 * s8 + half;
            if (s8 < 7) {
                // stage chunk c+2 from prefetch regs
                uint32_t* An = As + ((c + 2) & 3) * ACH_WORDS;
                #pragma unroll
                for (int i = 0; i < 4; i++)
                    An[sw[i]] = packbf(pre[2 * i], pre[2 * i + 1]);
                // load chunk c+3
                if (c + 3 < 16) {
                    const float* xn = xpix + (size_t)(c + 3) * (16 * HW);
                    #pragma unroll
                    for (int i = 0; i < 4; i++) {
                        pre[2 * i]     = xn[(size_t)i * 4 * HW];
                        pre[2 * i + 1] = xn[(size_t)i * 4 * HW + HW];
                    }
                }
            }
            // MMA on chunk c
            const uint32_t* Ac = As + (c & 3) * ACH_WORDS;
            uint2 afr[2][2];
            #pragma unroll
            for (int mtl = 0; mtl < 2; mtl++) {
                int mt = warp_m * 2 + mtl;
                int lr = ((lane + mt * 2) & 31) * 2;
                afr[mtl][0] = *reinterpret_cast<const uint2*>(Ac + mt * 128 + lr);
                afr[mtl][1] = *reinterpret_cast<const uint2*>(Ac + mt * 128 + 64 + lr);
            }
            uint2 bfr[4];
            #pragma unroll
            for (int ntl = 0; ntl < 4; ntl++)
                bfr[ntl] = *reinterpret_cast<const uint2*>(
                    Bp + (c * 8 + warp_n * 4 + ntl) * 64 + lane * 2);
            #pragma unroll
            for (int mtl = 0; mtl < 2; mtl++)
                #pragma unroll
                for (int ntl = 0; ntl < 4; ntl++) {
                    asm volatile(
                        "mma.sync.aligned.m16n8k16.row.col.f32.bf16.bf16.f32 "
                        "{%0,%1,%2,%3}, {%4,%5,%6,%7}, {%8,%9}, {%0,%1,%2,%3};"
                        : "+f"(acc[mtl][ntl][0]), "+f"(acc[mtl][ntl][1]),
                          "+f"(acc[mtl][ntl][2]), "+f"(acc[mtl][ntl][3])
                        : "r"(afr[mtl][0].x), "r"(afr[mtl][0].y),
                          "r"(afr[mtl][1].x), "r"(afr[mtl][1].y),
                          "r"(bfr[ntl].x), "r"(bfr[ntl].y));
                }
        }
        __syncthreads();
    }

    // ---- Phase 2: kq = w_sim * relu(key) ----
    #pragma unroll
    for (int mtl = 0; mtl < 2; mtl++) {
        float pa[4] = {0, 0, 0, 0}, pb[4] = {0, 0, 0, 0};
        #pragma unroll
        for (int ntl = 0; ntl < 4; ntl++) {
            int col0 = warp_n * 32 + ntl * 8 + 2 * tig;
            float v0 = fmaxf(acc[mtl][ntl][0], 0.f);
            float v1 = fmaxf(acc[mtl][ntl][1], 0.f);
            float v2 = fmaxf(acc[mtl][ntl][2], 0.f);
            float v3 = fmaxf(acc[mtl][ntl][3], 0.f);
            #pragma unroll
            for (int s = 0; s < 4; s++) {
                float w0 = wsim_s[s * 64 + col0];
                float w1 = wsim_s[s * 64 + col0 + 1];
                pa[s] += v0 * w0 + v1 * w1;
                pb[s] += v2 * w0 + v3 * w1;
            }
        }
        #pragma unroll
        for (int s = 0; s < 4; s++) {
            pa[s] += __shfl_xor_sync(0xffffffffu, pa[s], 1);
            pa[s] += __shfl_xor_sync(0xffffffffu, pa[s], 2);
            pb[s] += __shfl_xor_sync(0xffffffffu, pb[s], 1);
            pb[s] += __shfl_xor_sync(0xffffffffu, pb[s], 2);
        }
        float va = (tig == 0) ? pa[0] : (tig == 1) ? pa[1] : (tig == 2) ? pa[2] : pa[3];
        float vb = (tig == 0) ? pb[0] : (tig == 1) ? pb[1] : (tig == 2) ? pb[2] : pb[3];
        int r0 = warp_m * 32 + mtl * 16 + gid;
        float* plane = kq2 + warp_n * 128 * KQ_STRIDE;
        plane[r0 * KQ_STRIDE + tig]       = va;
        plane[(r0 + 8) * KQ_STRIDE + tig] = vb;
    }
    __syncthreads();

    // ---- Phase 3: per-window softmax; output to aw[(p*8+win)*4+q] ----
    if (tid < 32) {
        int win = tid >> 2, s = tid & 3;
        float vals[16];
        float mx = -3.4e38f;
        #pragma unroll
        for (int p = 0; p < 16; p++) {
            int mm = (p >> 2) * 32 + win * 4 + (p & 3);
            float v = (kq2[mm * KQ_STRIDE + s] +
                       kq2[128 * KQ_STRIDE + mm * KQ_STRIDE + s]) * 0.25f;
            vals[p] = v;
            mx = fmaxf(mx, v);
        }
        float sum = 0.f;
        #pragma unroll
        for (int p = 0; p < 16; p++) { vals[p] = __expf(vals[p] - mx); sum += vals[p]; }
        float inv = 1.f / sum;
        #pragma unroll
        for (int p = 0; p < 16; p++)
            aw[(p * 8 + win) * 4 + s] = vals[p] * inv;
    }
    __syncthreads();

    // ---- Phase 4: aggregation, 2 channel-passes per weight load ----
    {
        const int win = tid & 7;
        const int cb  = tid >> 3;
        const float* xa = x + (size_t)n * C_ * HW + (size_t)(hb * 4) * W_
                          + wq * 32 + win * 4 + (size_t)cb * HW;
        float* obase = out + ((size_t)n * C_ * 64 + hb * 2) * 64 + wq * 16 + win * 2
                     + (size_t)cb * 64 * 64;
        const float* awin = aw + win * 4;
        #pragma unroll
        for (int pp = 0; pp < 4; pp++) {
            const float* xp = xa + (size_t)(pp * 64) * HW;
            float oa0 = 0.f, oa1 = 0.f, oa2 = 0.f, oa3 = 0.f;
            float ob0 = 0.f, ob1 = 0.f, ob2 = 0.f, ob3 = 0.f;
            #pragma unroll
            for (int i = 0; i < 4; i++) {
                float4 w0 = *reinterpret_cast<const float4*>(awin + (i * 4 + 0) * 32);
                float4 w1 = *reinterpret_cast<const float4*>(awin + (i * 4 + 1) * 32);
                float4 w2 = *reinterpret_cast<const float4*>(awin + (i * 4 + 2) * 32);
                float4 w3 = *reinterpret_cast<const float4*>(awin + (i * 4 + 3) * 32);
                float4 va = *reinterpret_cast<const float4*>(xp + i * W_);
                float4 vb = *reinterpret_cast<const float4*>(
                    xp + (size_t)32 * HW + i * W_);
                oa0 += va.x * w0.x + va.y * w1.x + va.z * w2.x + va.w * w3.x;
                oa1 += va.x * w0.y + va.y * w1.y + va.z * w2.y + va.w * w3.y;
                oa2 += va.x * w0.z + va.y * w1.z + va.z * w2.z + va.w * w3.z;
                oa3 += va.x * w0.w + va.y * w1.w + va.z * w2.w + va.w * w3.w;
                ob0 += vb.x * w0.x + vb.y * w1.x + vb.z * w2.x + vb.w * w3.x;
                ob1 += vb.x * w0.y + vb.y * w1.y + vb.z * w2.y + vb.w * w3.y;
                ob2 += vb.x * w0.z + vb.y * w1.z + vb.z * w2.z + vb.w * w3.z;
                ob3 += vb.x * w0.w + vb.y * w1.w + vb.z * w2.w + vb.w * w3.w;
            }
            float* op0 = obase + (size_t)(pp * 64) * 4096;
            float* op1 = op0 + (size_t)32 * 4096;
            *reinterpret_cast<float2*>(op0)      = make_float2(oa0, oa1);
            *reinterpret_cast<float2*>(op0 + 64) = make_float2(oa2, oa3);
            *reinterpret_cast<float2*>(op1)      = make_float2(ob0, ob1);
            *reinterpret_cast<float2*>(op1 + 64) = make_float2(ob2, ob3);
        }
    }
}

extern "C" void kernel_launch(void* const* d_in, const int* in_sizes, int n_in,
                              void* d_out, int out_size) {
    const float* x  = (const float*)d_in[0];
    const float* wk = (const float*)d_in[1];
    const float* ws = (const float*)d_in[2];
    float* out = (float*)d_out;

    const int smem_bytes = (BP_WORDS + 4 * ACH_WORDS) * 4
                         + (2 * 128 * KQ_STRIDE + 256 + 512) * 4;   // 57344 B
    cudaFuncSetAttribute(frac_downsample_kernel,
                         cudaFuncAttributeMaxDynamicSharedMemorySize, smem_bytes);

    frac_downsample_kernel<<<2048, 256, smem_bytes>>>(x, wk, ws, out);
}

// round 8
// speedup vs baseline: 1.3608x; 1.0361x over previous
#include <cuda_runtime.h>
#include <cuda_bf16.h>
#include <cstdint>

// FracDownSample fused kernel v7 (sm_103a).
// x:[16,256,128,128] f32, w_key:[64,256], w_sim:[4,64] -> out:[16,256,64,64] f32
//
// vs v6:
//  - B packed in 2-kstep uint4 blocks -> 4 LDS.128 per super-iter (was 8 LDS.64)
//  - phase-1 staging loads are float2 (4 LDG.64/chunk, was 8 LDG.32)
//  - phase-4 shares weights across 4 channel passes (16 weight LDS.128, MLP-4)

#define H_ 128
#define W_ 128
#define C_ 256
#define HW (H_ * W_)
#define KQ_STRIDE 5

#define BP_WORDS  8192           // 8 c2-blocks * 8 ntiles * 128 words
#define ACH_WORDS 1024           // one 16-ch chunk, fragment-packed bf16x2

__device__ __forceinline__ uint32_t packbf(float lo, float hi) {
    __nv_bfloat162 v = __floats2bfloat162_rn(lo, hi);
    return *reinterpret_cast<uint32_t*>(&v);
}

__global__ __launch_bounds__(256, 3)
void frac_downsample_kernel(const float* __restrict__ x,
                            const float* __restrict__ w_key,
                            const float* __restrict__ w_sim,
                            float* __restrict__ out) {
    extern __shared__ uint32_t smem[];
    uint32_t* Bp     = smem;                          // 8192 w (32 KB)
    uint32_t* As     = Bp + BP_WORDS;                 // 4*1024 w (16 KB ring)
    float*    kq2    = (float*)(As + 4 * ACH_WORDS);  // 2 planes * 128*5
    float*    wsim_s = kq2 + 2 * 128 * KQ_STRIDE;     // 256
    float*    aw     = wsim_s + 256;                  // 16*8*4 floats, 16B-aligned

    const int tid = threadIdx.x;
    const int bid = blockIdx.x;
    const int n  = bid >> 7;
    const int hb = (bid >> 2) & 31;
    const int wq = bid & 3;

    const float* xbase = x + ((size_t)n * C_ * H_ + (size_t)hb * 4) * W_ + wq * 32;

    // ---- stage B (w_key): 2-kstep uint4 blocks of bf16x2 fragments ----
    // word for (kstep s, ntile nt, group g, tig, khalf):
    //   ((s>>1)*8 + nt)*128 + (g*4+tig)*4 + (s&1)*2 + kh
    {
        const int c    = (tid & 127) * 2;       // even channel
        const int s    = c >> 4;
        const int kkc  = c & 15;
        const int tigc = (kkc >> 1) & 3;
        const int kh   = kkc >> 3;
        const int rb   = tid >> 7;
        const int base = ((s >> 1) * 8) * 128 + (s & 1) * 2 + kh;
        #pragma unroll 8
        for (int rr = 0; rr < 32; rr++) {
            int r = rr * 2 + rb;
            int nt = r >> 3, g = r & 7;
            Bp[base + nt * 128 + (g * 4 + tigc) * 4] =
                packbf(w_key[r * 256 + c], w_key[r * 256 + c + 1]);
        }
    }
    wsim_s[tid] = w_sim[tid];

    // ---- per-thread A staging geometry (float2 pixel-pair scheme) ----
    // thread owns pixels (pix2, pix2+1) and channel pairs {cpair, cpair+4}.
    const int cpair = tid >> 6;                 // 0..3  (tig_s = cpair)
    const int pix2  = (tid & 63) * 2;
    const float* xpix = xbase + (pix2 >> 5) * W_ + (pix2 & 31);
    const size_t gl0 = (size_t)(2 * cpair) * HW;        // h=0 channels
    const size_t gl1 = (size_t)(2 * cpair + 8) * HW;    // h=1 channels
    int sw[4];                                   // [h*2 + j]
    {
        const int mtile = pix2 >> 4;
        #pragma unroll
        for (int j = 0; j < 2; j++) {
            int ml = (pix2 + j) & 15;
            int gid_s = ml & 7, b1 = ml >> 3;
            int lane_r = ((gid_s * 4 + cpair) + mtile * 2) & 31;
            int off = lane_r * 2 + b1;
            sw[j]     = mtile * 128 + off;        // kh_s = 0
            sw[2 + j] = mtile * 128 + 64 + off;   // kh_s = 1
        }
    }

    // ---- prologue: chunks 0,1 direct to ring; chunk 2 into prefetch regs ----
    float2 pre[4];
    #pragma unroll
    for (int ck = 0; ck < 2; ck++) {
        const float* xc = xpix + (size_t)ck * (16 * HW);
        float2 l0 = *(const float2*)(xc + gl0);
        float2 h0 = *(const float2*)(xc + gl0 + HW);
        float2 l1 = *(const float2*)(xc + gl1);
        float2 h1 = *(const float2*)(xc + gl1 + HW);
        uint32_t* An = As + ck * ACH_WORDS;
        An[sw[0]] = packbf(l0.x, h0.x);
        An[sw[1]] = packbf(l0.y, h0.y);
        An[sw[2]] = packbf(l1.x, h1.x);
        An[sw[3]] = packbf(l1.y, h1.y);
    }
    {
        const float* xc = xpix + (size_t)2 * (16 * HW);
        pre[0] = *(const float2*)(xc + gl0);
        pre[1] = *(const float2*)(xc + gl0 + HW);
        pre[2] = *(const float2*)(xc + gl1);
        pre[3] = *(const float2*)(xc + gl1 + HW);
    }
    __syncthreads();

    const int warp = tid >> 5, lane = tid & 31;
    const int warp_m = warp & 3;
    const int warp_n = warp >> 2;
    const int gid = lane >> 2, tig = lane & 3;

    float acc[2][4][4];
    #pragma unroll
    for (int a = 0; a < 2; a++)
        #pragma unroll
        for (int b = 0; b < 4; b++)
            acc[a][b][0] = acc[a][b][1] = acc[a][b][2] = acc[a][b][3] = 0.f;

    // ---- Phase 1: 8 super-iterations (2 ksteps per barrier) ----
    for (int c2 = 0; c2 < 8; c2++) {
        uint4 bq[4];
        #pragma unroll
        for (int ntl = 0; ntl < 4; ntl++)
            bq[ntl] = *(const uint4*)(
                Bp + (c2 * 8 + warp_n * 4 + ntl) * 128 + lane * 4);
        #pragma unroll
        for (int half = 0; half < 2; half++) {
            const int c = 2 * c2 + half;
            if (c + 2 < 16) {
                uint32_t* An = As + ((c + 2) & 3) * ACH_WORDS;
                An[sw[0]] = packbf(pre[0].x, pre[1].x);
                An[sw[1]] = packbf(pre[0].y, pre[1].y);
                An[sw[2]] = packbf(pre[2].x, pre[3].x);
                An[sw[3]] = packbf(pre[2].y, pre[3].y);
                if (c + 3 < 16) {
                    const float* xn = xpix + (size_t)(c + 3) * (16 * HW);
                    pre[0] = *(const float2*)(xn + gl0);
                    pre[1] = *(const float2*)(xn + gl0 + HW);
                    pre[2] = *(const float2*)(xn + gl1);
                    pre[3] = *(const float2*)(xn + gl1 + HW);
                }
            }
            const uint32_t* Ac = As + (c & 3) * ACH_WORDS;
            uint2 afr[2][2];
            #pragma unroll
            for (int mtl = 0; mtl < 2; mtl++) {
                int mt = warp_m * 2 + mtl;
                int lr = ((lane + mt * 2) & 31) * 2;
                afr[mtl][0] = *reinterpret_cast<const uint2*>(Ac + mt * 128 + lr);
                afr[mtl][1] = *reinterpret_cast<const uint2*>(Ac + mt * 128 + 64 + lr);
            }
            #pragma unroll
            for (int mtl = 0; mtl < 2; mtl++)
                #pragma unroll
                for (int ntl = 0; ntl < 4; ntl++) {
                    uint32_t bx = half ? bq[ntl].z : bq[ntl].x;
                    uint32_t by = half ? bq[ntl].w : bq[ntl].y;
                    asm volatile(
                        "mma.sync.aligned.m16n8k16.row.col.f32.bf16.bf16.f32 "
                        "{%0,%1,%2,%3}, {%4,%5,%6,%7}, {%8,%9}, {%0,%1,%2,%3};"
                        : "+f"(acc[mtl][ntl][0]), "+f"(acc[mtl][ntl][1]),
                          "+f"(acc[mtl][ntl][2]), "+f"(acc[mtl][ntl][3])
                        : "r"(afr[mtl][0].x), "r"(afr[mtl][0].y),
                          "r"(afr[mtl][1].x), "r"(afr[mtl][1].y),
                          "r"(bx), "r"(by));
                }
        }
        __syncthreads();
    }

    // ---- Phase 2: kq = w_sim * relu(key) ----
    #pragma unroll
    for (int mtl = 0; mtl < 2; mtl++) {
        float pa[4] = {0, 0, 0, 0}, pb[4] = {0, 0, 0, 0};
        #pragma unroll
        for (int ntl = 0; ntl < 4; ntl++) {
            int col0 = warp_n * 32 + ntl * 8 + 2 * tig;
            float v0 = fmaxf(acc[mtl][ntl][0], 0.f);
            float v1 = fmaxf(acc[mtl][ntl][1], 0.f);
            float v2 = fmaxf(acc[mtl][ntl][2], 0.f);
            float v3 = fmaxf(acc[mtl][ntl][3], 0.f);
            #pragma unroll
            for (int s = 0; s < 4; s++) {
                float w0 = wsim_s[s * 64 + col0];
                float w1 = wsim_s[s * 64 + col0 + 1];
                pa[s] += v0 * w0 + v1 * w1;
                pb[s] += v2 * w0 + v3 * w1;
            }
        }
        #pragma unroll
        for (int s = 0; s < 4; s++) {
            pa[s] += __shfl_xor_sync(0xffffffffu, pa[s], 1);
            pa[s] += __shfl_xor_sync(0xffffffffu, pa[s], 2);
            pb[s] += __shfl_xor_sync(0xffffffffu, pb[s], 1);
            pb[s] += __shfl_xor_sync(0xffffffffu, pb[s], 2);
        }
        float va = (tig == 0) ? pa[0] : (tig == 1) ? pa[1] : (tig == 2) ? pa[2] : pa[3];
        float vb = (tig == 0) ? pb[0] : (tig == 1) ? pb[1] : (tig == 2) ? pb[2] : pb[3];
        int r0 = warp_m * 32 + mtl * 16 + gid;
        float* plane = kq2 + warp_n * 128 * KQ_STRIDE;
        plane[r0 * KQ_STRIDE + tig]       = va;
        plane[(r0 + 8) * KQ_STRIDE + tig] = vb;
    }
    __syncthreads();

    // ---- Phase 3: per-window softmax; output to aw[(p*8+win)*4+q] ----
    if (tid < 32) {
        int win = tid >> 2, s = tid & 3;
        float vals[16];
        float mx = -3.4e38f;
        #pragma unroll
        for (int p = 0; p < 16; p++) {
            int mm = (p >> 2) * 32 + win * 4 + (p & 3);
            float v = (kq2[mm * KQ_STRIDE + s] +
                       kq2[128 * KQ_STRIDE + mm * KQ_STRIDE + s]) * 0.25f;
            vals[p] = v;
            mx = fmaxf(mx, v);
        }
        float sum = 0.f;
        #pragma unroll
        for (int p = 0; p < 16; p++) { vals[p] = __expf(vals[p] - mx); sum += vals[p]; }
        float inv = 1.f / sum;
        #pragma unroll
        for (int p = 0; p < 16; p++)
            aw[(p * 8 + win) * 4 + s] = vals[p] * inv;
    }
    __syncthreads();

    // ---- Phase 4: aggregation, 4 channel-passes per weight load ----
    {
        const int win = tid & 7;
        const int cb  = tid >> 3;
        const float* xa = x + (size_t)n * C_ * HW + (size_t)(hb * 4) * W_
                          + wq * 32 + win * 4 + (size_t)cb * HW;
        float* obase = out + ((size_t)n * C_ * 64 + hb * 2) * 64 + wq * 16 + win * 2
                     + (size_t)cb * 4096;
        const float* awin = aw + win * 4;
        #pragma unroll
        for (int pp = 0; pp < 2; pp++) {
            const float* xp = xa + (size_t)(pp * 128) * HW;
            float o[4][4];
            #pragma unroll
            for (int j = 0; j < 4; j++)
                o[j][0] = o[j][1] = o[j][2] = o[j][3] = 0.f;
            #pragma unroll
            for (int i = 0; i < 4; i++) {
                float4 w0 = *reinterpret_cast<const float4*>(awin + (i * 4 + 0) * 32);
                float4 w1 = *reinterpret_cast<const float4*>(awin + (i * 4 + 1) * 32);
                float4 w2 = *reinterpret_cast<const float4*>(awin + (i * 4 + 2) * 32);
                float4 w3 = *reinterpret_cast<const float4*>(awin + (i * 4 + 3) * 32);
                float4 v0 = *reinterpret_cast<const float4*>(xp + i * W_);
                float4 v1 = *reinterpret_cast<const float4*>(xp + (size_t)32 * HW + i * W_);
                float4 v2 = *reinterpret_cast<const float4*>(xp + (size_t)64 * HW + i * W_);
                float4 v3 = *reinterpret_cast<const float4*>(xp + (size_t)96 * HW + i * W_);
                o[0][0] += v0.x * w0.x + v0.y * w1.x + v0.z * w2.x + v0.w * w3.x;
                o[0][1] += v0.x * w0.y + v0.y * w1.y + v0.z * w2.y + v0.w * w3.y;
                o[0][2] += v0.x * w0.z + v0.y * w1.z + v0.z * w2.z + v0.w * w3.z;
                o[0][3] += v0.x * w0.w + v0.y * w1.w + v0.z * w2.w + v0.w * w3.w;
                o[1][0] += v1.x * w0.x + v1.y * w1.x + v1.z * w2.x + v1.w * w3.x;
                o[1][1] += v1.x * w0.y + v1.y * w1.y + v1.z * w2.y + v1.w * w3.y;
                o[1][2] += v1.x * w0.z + v1.y * w1.z + v1.z * w2.z + v1.w * w3.z;
                o[1][3] += v1.x * w0.w + v1.y * w1.w + v1.z * w2.w + v1.w * w3.w;
                o[2][0] += v2.x * w0.x + v2.y * w1.x + v2.z * w2.x + v2.w * w3.x;
                o[2][1] += v2.x * w0.y + v2.y * w1.y + v2.z * w2.y + v2.w * w3.y;
                o[2][2] += v2.x * w0.z + v2.y * w1.z + v2.z * w2.z + v2.w * w3.z;
                o[2][3] += v2.x * w0.w + v2.y * w1.w + v2.z * w2.w + v2.w * w3.w;
                o[3][0] += v3.x * w0.x + v3.y * w1.x + v3.z * w2.x + v3.w * w3.x;
                o[3][1] += v3.x * w0.y + v3.y * w1.y + v3.z * w2.y + v3.w * w3.y;
                o[3][2] += v3.x * w0.z + v3.y * w1.z + v3.z * w2.z + v3.w * w3.z;
                o[3][3] += v3.x * w0.w + v3.y * w1.w + v3.z * w2.w + v3.w * w3.w;
            }
            #pragma unroll
            for (int j = 0; j < 4; j++) {
                float* op = obase + (size_t)(pp * 128 + j * 32) * 4096;
                *reinterpret_cast<float2*>(op)      = make_float2(o[j][0], o[j][1]);
                *reinterpret_cast<float2*>(op + 64) = make_float2(o[j][2], o[j][3]);
            }
        }
    }
}

extern "C" void kernel_launch(void* const* d_in, const int* in_sizes, int n_in,
                              void* d_out, int out_size) {
    const float* x  = (const float*)d_in[0];
    const float* wk = (const float*)d_in[1];
    const float* ws = (const float*)d_in[2];
    float* out = (float*)d_out;

    const int smem_bytes = (BP_WORDS + 4 * ACH_WORDS) * 4
                         + (2 * 128 * KQ_STRIDE + 256 + 512) * 4;   // 57344 B
    cudaFuncSetAttribute(frac_downsample_kernel,
                         cudaFuncAttributeMaxDynamicSharedMemorySize, smem_bytes);

    frac_downsample_kernel<<<2048, 256, smem_bytes>>>(x, wk, ws, out);
}

// round 10
// speedup vs baseline: 1.3949x; 1.0251x over previous
#include <cuda_runtime.h>
#include <cuda_bf16.h>
#include <cstdint>

// FracDownSample fused kernel v9 (sm_103a).
// x:[16,256,128,128] f32, w_key:[64,256], w_sim:[4,64] -> out:[16,256,64,64] f32
//
// v8 + fix: cp.async commit group issued EVERY iteration (empty groups after
// chunk 15) so wait_group<1> at iters 13..15 still covers the final chunk.
// v8's bug: fixed committed-count after iter 12 meant wait_group<1> at iter 14
// did not guarantee chunk 15 had landed before packing it.

#define H_ 128
#define W_ 128
#define C_ 256
#define HW (H_ * W_)
#define KQ_STRIDE 5

#define BP_WORDS   8192          // 8 c2-blocks * 8 ntiles * 128 words (uint4 B)
#define PCH_WORDS  1024          // packed bf16x2 chunk (16 ch)
#define RAW_WORDS  2048          // raw f32 chunk (16 ch * 128 px)

__device__ __forceinline__ uint32_t packbf(float lo, float hi) {
    __nv_bfloat162 v = __floats2bfloat162_rn(lo, hi);
    return *reinterpret_cast<uint32_t*>(&v);
}

__device__ __forceinline__ void cp_async16(uint32_t smem_addr, const void* gptr) {
    asm volatile("cp.async.cg.shared.global [%0], [%1], 16;"
                 :: "r"(smem_addr), "l"(gptr) : "memory");
}
__device__ __forceinline__ void cp_commit() {
    asm volatile("cp.async.commit_group;" ::: "memory");
}
template <int N>
__device__ __forceinline__ void cp_wait() {
    asm volatile("cp.async.wait_group %0;" :: "n"(N) : "memory");
}

__global__ __launch_bounds__(256, 3)
void frac_downsample_kernel(const float* __restrict__ x,
                            const float* __restrict__ w_key,
                            const float* __restrict__ w_sim,
                            float* __restrict__ out) {
    extern __shared__ uint32_t smem[];
    uint32_t* Bp     = smem;                            // 32 KB
    uint32_t* Pk     = Bp + BP_WORDS;                   // 2 * 4 KB packed ring
    float*    Raw    = (float*)(Pk + 2 * PCH_WORDS);    // 3 * 8 KB raw ring
    float*    kq2    = Raw + 3 * RAW_WORDS;             // 2 planes * 128*5
    float*    wsim_s = kq2 + 2 * 128 * KQ_STRIDE;       // 256
    float*    aw     = wsim_s + 256;                    // 512, 16B-aligned

    const int tid = threadIdx.x;
    const int bid = blockIdx.x;
    const int n  = bid >> 7;
    const int hb = (bid >> 2) & 31;
    const int wq = bid & 3;

    const float* xbase = x + ((size_t)n * C_ * H_ + (size_t)hb * 4) * W_ + wq * 32;

    // ---- cp.async geometry: thread copies uint4 u = tid and tid+256 ----
    const int u0 = tid, u1 = tid + 256;
    const size_t cg0 = (size_t)(u0 >> 5) * HW + ((u0 & 31) >> 3) * W_ + (u0 & 7) * 4;
    const size_t cg1 = (size_t)(u1 >> 5) * HW + ((u1 & 31) >> 3) * W_ + (u1 & 7) * 4;
    uint32_t raw_s0[3], raw_s1[3];
    #pragma unroll
    for (int r = 0; r < 3; r++) {
        raw_s0[r] = (uint32_t)__cvta_generic_to_shared(Raw + r * RAW_WORDS + u0 * 4);
        raw_s1[r] = (uint32_t)__cvta_generic_to_shared(Raw + r * RAW_WORDS + u1 * 4);
    }

    // ---- issue chunks 0,1,2 ----
    #pragma unroll
    for (int ck = 0; ck < 3; ck++) {
        const float* xc = xbase + (size_t)ck * (16 * HW);
        cp_async16(raw_s0[ck], xc + cg0);
        cp_async16(raw_s1[ck], xc + cg1);
        cp_commit();
    }

    // ---- stage B (w_key): 2-kstep uint4 blocks of bf16x2 fragments ----
    {
        const int c    = (tid & 127) * 2;
        const int s    = c >> 4;
        const int kkc  = c & 15;
        const int tigc = (kkc >> 1) & 3;
        const int kh   = kkc >> 3;
        const int rb   = tid >> 7;
        const int base = ((s >> 1) * 8) * 128 + (s & 1) * 2 + kh;
        #pragma unroll 8
        for (int rr = 0; rr < 32; rr++) {
            int r = rr * 2 + rb;
            int nt = r >> 3, g = r & 7;
            Bp[base + nt * 128 + (g * 4 + tigc) * 4] =
                packbf(w_key[r * 256 + c], w_key[r * 256 + c + 1]);
        }
    }
    wsim_s[tid] = w_sim[tid];

    // ---- pack geometry: thread owns pixel pair + channel pairs ----
    const int cpair = tid >> 6;                 // 0..3
    const int pix2  = (tid & 63) * 2;
    const int rch0 = 2 * cpair;
    const int rch1 = 2 * cpair + 8;
    int sw[4];
    {
        const int mtile = pix2 >> 4;
        #pragma unroll
        for (int j = 0; j < 2; j++) {
            int ml = (pix2 + j) & 15;
            int gid_s = ml & 7, b1 = ml >> 3;
            int lane_r = ((gid_s * 4 + cpair) + mtile * 2) & 31;
            int off = lane_r * 2 + b1;
            sw[j]     = mtile * 128 + off;
            sw[2 + j] = mtile * 128 + 64 + off;
        }
    }

    // ---- prologue: pack chunk 0 ----
    cp_wait<2>();
    __syncthreads();
    {
        const float* rb0 = Raw;
        float2 l0 = *(const float2*)(rb0 + rch0 * 128 + pix2);
        float2 h0 = *(const float2*)(rb0 + (rch0 + 1) * 128 + pix2);
        float2 l1 = *(const float2*)(rb0 + rch1 * 128 + pix2);
        float2 h1 = *(const float2*)(rb0 + (rch1 + 1) * 128 + pix2);
        Pk[sw[0]] = packbf(l0.x, h0.x);
        Pk[sw[1]] = packbf(l0.y, h0.y);
        Pk[sw[2]] = packbf(l1.x, h1.x);
        Pk[sw[3]] = packbf(l1.y, h1.y);
    }

    const int warp = tid >> 5, lane = tid & 31;
    const int warp_m = warp & 3;
    const int warp_n = warp >> 2;
    const int gid = lane >> 2, tig = lane & 3;

    float acc[2][4][4];
    #pragma unroll
    for (int a = 0; a < 2; a++)
        #pragma unroll
        for (int b = 0; b < 4; b++)
            acc[a][b][0] = acc[a][b][1] = acc[a][b][2] = acc[a][b][3] = 0.f;

    // ---- Phase 1: 16 ksteps; cp.async 3 ahead, pack 1 ahead ----
    // A commit group is issued EVERY iteration (empty after chunk 15), so at
    // top of iter c the committed count is 3+c and wait_group<1> always
    // guarantees chunks 0..c+1 have landed (incl. chunk 15 at iter 14).
    uint4 bq[4];
    static const int mod3[19] = {0,1,2,0,1,2,0,1,2,0,1,2,0,1,2,0,1,2,0};
    #pragma unroll
    for (int c = 0; c < 16; c++) {
        cp_wait<1>();
        __syncthreads();
        if (c + 3 < 16) {
            const float* xc = xbase + (size_t)(c + 3) * (16 * HW);
            int slot = mod3[c + 3];
            cp_async16(raw_s0[slot], xc + cg0);
            cp_async16(raw_s1[slot], xc + cg1);
        }
        cp_commit();   // unconditional: keeps the wait-window arithmetic valid
        if (c + 1 < 16) {
            const float* rb = Raw + mod3[c + 1] * RAW_WORDS;
            float2 l0 = *(const float2*)(rb + rch0 * 128 + pix2);
            float2 h0 = *(const float2*)(rb + (rch0 + 1) * 128 + pix2);
            float2 l1 = *(const float2*)(rb + rch1 * 128 + pix2);
            float2 h1 = *(const float2*)(rb + (rch1 + 1) * 128 + pix2);
            uint32_t* Pn = Pk + ((c + 1) & 1) * PCH_WORDS;
            Pn[sw[0]] = packbf(l0.x, h0.x);
            Pn[sw[1]] = packbf(l0.y, h0.y);
            Pn[sw[2]] = packbf(l1.x, h1.x);
            Pn[sw[3]] = packbf(l1.y, h1.y);
        }
        if ((c & 1) == 0) {
            #pragma unroll
            for (int ntl = 0; ntl < 4; ntl++)
                bq[ntl] = *(const uint4*)(
                    Bp + ((c >> 1) * 8 + warp_n * 4 + ntl) * 128 + lane * 4);
        }
        const uint32_t* Ac = Pk + (c & 1) * PCH_WORDS;
        uint2 afr[2][2];
        #pragma unroll
        for (int mtl = 0; mtl < 2; mtl++) {
            int mt = warp_m * 2 + mtl;
            int lr = ((lane + mt * 2) & 31) * 2;
            afr[mtl][0] = *reinterpret_cast<const uint2*>(Ac + mt * 128 + lr);
            afr[mtl][1] = *reinterpret_cast<const uint2*>(Ac + mt * 128 + 64 + lr);
        }
        #pragma unroll
        for (int mtl = 0; mtl < 2; mtl++)
            #pragma unroll
            for (int ntl = 0; ntl < 4; ntl++) {
                uint32_t bx = (c & 1) ? bq[ntl].z : bq[ntl].x;
                uint32_t by = (c & 1) ? bq[ntl].w : bq[ntl].y;
                asm volatile(
                    "mma.sync.aligned.m16n8k16.row.col.f32.bf16.bf16.f32 "
                    "{%0,%1,%2,%3}, {%4,%5,%6,%7}, {%8,%9}, {%0,%1,%2,%3};"
                    : "+f"(acc[mtl][ntl][0]), "+f"(acc[mtl][ntl][1]),
                      "+f"(acc[mtl][ntl][2]), "+f"(acc[mtl][ntl][3])
                    : "r"(afr[mtl][0].x), "r"(afr[mtl][0].y),
                      "r"(afr[mtl][1].x), "r"(afr[mtl][1].y),
                      "r"(bx), "r"(by));
            }
    }
    __syncthreads();

    // ---- Phase 2: kq = w_sim * relu(key) ----
    #pragma unroll
    for (int mtl = 0; mtl < 2; mtl++) {
        float pa[4] = {0, 0, 0, 0}, pb[4] = {0, 0, 0, 0};
        #pragma unroll
        for (int ntl = 0; ntl < 4; ntl++) {
            int col0 = warp_n * 32 + ntl * 8 + 2 * tig;
            float v0 = fmaxf(acc[mtl][ntl][0], 0.f);
            float v1 = fmaxf(acc[mtl][ntl][1], 0.f);
            float v2 = fmaxf(acc[mtl][ntl][2], 0.f);
            float v3 = fmaxf(acc[mtl][ntl][3], 0.f);
            #pragma unroll
            for (int s = 0; s < 4; s++) {
                float w0 = wsim_s[s * 64 + col0];
                float w1 = wsim_s[s * 64 + col0 + 1];
                pa[s] += v0 * w0 + v1 * w1;
                pb[s] += v2 * w0 + v3 * w1;
            }
        }
        #pragma unroll
        for (int s = 0; s < 4; s++) {
            pa[s] += __shfl_xor_sync(0xffffffffu, pa[s], 1);
            pa[s] += __shfl_xor_sync(0xffffffffu, pa[s], 2);
            pb[s] += __shfl_xor_sync(0xffffffffu, pb[s], 1);
            pb[s] += __shfl_xor_sync(0xffffffffu, pb[s], 2);
        }
        float va = (tig == 0) ? pa[0] : (tig == 1) ? pa[1] : (tig == 2) ? pa[2] : pa[3];
        float vb = (tig == 0) ? pb[0] : (tig == 1) ? pb[1] : (tig == 2) ? pb[2] : pb[3];
        int r0 = warp_m * 32 + mtl * 16 + gid;
        float* plane = kq2 + warp_n * 128 * KQ_STRIDE;
        plane[r0 * KQ_STRIDE + tig]       = va;
        plane[(r0 + 8) * KQ_STRIDE + tig] = vb;
    }
    __syncthreads();

    // ---- Phase 3: per-window softmax; output to aw[(p*8+win)*4+q] ----
    if (tid < 32) {
        int win = tid >> 2, s = tid & 3;
        float vals[16];
        float mx = -3.4e38f;
        #pragma unroll
        for (int p = 0; p < 16; p++) {
            int mm = (p >> 2) * 32 + win * 4 + (p & 3);
            float v = (kq2[mm * KQ_STRIDE + s] +
                       kq2[128 * KQ_STRIDE + mm * KQ_STRIDE + s]) * 0.25f;
            vals[p] = v;
            mx = fmaxf(mx, v);
        }
        float sum = 0.f;
        #pragma unroll
        for (int p = 0; p < 16; p++) { vals[p] = __expf(vals[p] - mx); sum += vals[p]; }
        float inv = 1.f / sum;
        #pragma unroll
        for (int p = 0; p < 16; p++)
            aw[(p * 8 + win) * 4 + s] = vals[p] * inv;
    }
    __syncthreads();

    // ---- Phase 4: aggregation, 4 channel-passes per weight load ----
    {
        const int win = tid & 7;
        const int cb  = tid >> 3;
        const float* xa = x + (size_t)n * C_ * HW + (size_t)(hb * 4) * W_
                          + wq * 32 + win * 4 + (size_t)cb * HW;
        float* obase = out + ((size_t)n * C_ * 64 + hb * 2) * 64 + wq * 16 + win * 2
                     + (size_t)cb * 4096;
        const float* awin = aw + win * 4;
        #pragma unroll
        for (int pp = 0; pp < 2; pp++) {
            const float* xp = xa + (size_t)(pp * 128) * HW;
            float o[4][4];
            #pragma unroll
            for (int j = 0; j < 4; j++)
                o[j][0] = o[j][1] = o[j][2] = o[j][3] = 0.f;
            #pragma unroll
            for (int i = 0; i < 4; i++) {
                float4 w0 = *reinterpret_cast<const float4*>(awin + (i * 4 + 0) * 32);
                float4 w1 = *reinterpret_cast<const float4*>(awin + (i * 4 + 1) * 32);
                float4 w2 = *reinterpret_cast<const float4*>(awin + (i * 4 + 2) * 32);
                float4 w3 = *reinterpret_cast<const float4*>(awin + (i * 4 + 3) * 32);
                float4 v0 = *reinterpret_cast<const float4*>(xp + i * W_);
                float4 v1 = *reinterpret_cast<const float4*>(xp + (size_t)32 * HW + i * W_);
                float4 v2 = *reinterpret_cast<const float4*>(xp + (size_t)64 * HW + i * W_);
                float4 v3 = *reinterpret_cast<const float4*>(xp + (size_t)96 * HW + i * W_);
                o[0][0] += v0.x * w0.x + v0.y * w1.x + v0.z * w2.x + v0.w * w3.x;
                o[0][1] += v0.x * w0.y + v0.y * w1.y + v0.z * w2.y + v0.w * w3.y;
                o[0][2] += v0.x * w0.z + v0.y * w1.z + v0.z * w2.z + v0.w * w3.z;
                o[0][3] += v0.x * w0.w + v0.y * w1.w + v0.z * w2.w + v0.w * w3.w;
                o[1][0] += v1.x * w0.x + v1.y * w1.x + v1.z * w2.x + v1.w * w3.x;
                o[1][1] += v1.x * w0.y + v1.y * w1.y + v1.z * w2.y + v1.w * w3.y;
                o[1][2] += v1.x * w0.z + v1.y * w1.z + v1.z * w2.z + v1.w * w3.z;
                o[1][3] += v1.x * w0.w + v1.y * w1.w + v1.z * w2.w + v1.w * w3.w;
                o[2][0] += v2.x * w0.x + v2.y * w1.x + v2.z * w2.x + v2.w * w3.x;
                o[2][1] += v2.x * w0.y + v2.y * w1.y + v2.z * w2.y + v2.w * w3.y;
                o[2][2] += v2.x * w0.z + v2.y * w1.z + v2.z * w2.z + v2.w * w3.z;
                o[2][3] += v2.x * w0.w + v2.y * w1.w + v2.z * w2.w + v2.w * w3.w;
                o[3][0] += v3.x * w0.x + v3.y * w1.x + v3.z * w2.x + v3.w * w3.x;
                o[3][1] += v3.x * w0.y + v3.y * w1.y + v3.z * w2.y + v3.w * w3.y;
                o[3][2] += v3.x * w0.z + v3.y * w1.z + v3.z * w2.z + v3.w * w3.z;
                o[3][3] += v3.x * w0.w + v3.y * w1.w + v3.z * w2.w + v3.w * w3.w;
            }
            #pragma unroll
            for (int j = 0; j < 4; j++) {
                float* op = obase + (size_t)(pp * 128 + j * 32) * 4096;
                *reinterpret_cast<float2*>(op)      = make_float2(o[j][0], o[j][1]);
                *reinterpret_cast<float2*>(op + 64) = make_float2(o[j][2], o[j][3]);
            }
        }
    }
}

extern "C" void kernel_launch(void* const* d_in, const int* in_sizes, int n_in,
                              void* d_out, int out_size) {
    const float* x  = (const float*)d_in[0];
    const float* wk = (const float*)d_in[1];
    const float* ws = (const float*)d_in[2];
    float* out = (float*)d_out;

    const int smem_bytes = (BP_WORDS + 2 * PCH_WORDS + 3 * RAW_WORDS) * 4
                         + (2 * 128 * KQ_STRIDE + 256 + 512) * 4;   // 73728 B
    cudaFuncSetAttribute(frac_downsample_kernel,
                         cudaFuncAttributeMaxDynamicSharedMemorySize, smem_bytes);

    frac_downsample_kernel<<<2048, 256, smem_bytes>>>(x, wk, ws, out);
}